// round 9
// baseline (speedup 1.0000x reference)
// v8 — v7 with the k3 reset-vs-read race fixed (resets moved after the fill
// barrier, matching the proven v4 ordering) + 16B-aligned GEMM smem.
#include <cuda_runtime.h>

#define NN 1024
#define EE 1536
#define MAXDEG 64

#define FMA_F32X2(d, a, b, c) \
    asm("fma.rn.f32x2 %0, %1, %2, %3;" : "=l"(d) : "l"(a), "l"(b), "l"(c))
#define PACK_F32X2(out, lo, hi) \
    asm("mov.b64 %0, {%1, %2};" : "=l"(out) : "f"(lo), "f"(hi))
#define UNPACK_F32X2(lo, hi, in) \
    asm("mov.b64 {%0, %1}, %2;" : "=f"(lo), "=f"(hi) : "l"(in))

__device__ float g_h[8192 * 64];
__device__ float g_ew[8 * EE];
__device__ int   g_slot[EE];            // endpoint exch slot (0 = empty); re-zeroed by k3
__device__ int   g_deg[NN];             // zero at load; re-zeroed by k3
__device__ int   g_adj[NN * MAXDEG];    // packed: e | (o << 11)
__device__ float g_adjw[NN * MAXDEG];   // lap[i, o] for that entry

// ---------------------------------------------------------------------------
// K1: 384 blocks x 256 threads.
//   [0,256):   GEMM h = X@W, 32-row tiles, FFMA2, 8 cols x 1 row per thread
//   [256,352): extract: scan inc, resolve edges via atomicExch, prefetch lap
//   [352,384): ew[b,e] = edges[b,e,:] . evec
// ---------------------------------------------------------------------------
__global__ void __launch_bounds__(256) k1(
    const float* __restrict__ nodes,   // [8192,64]
    const float* __restrict__ edges,   // [8,1536,32]
    const float* __restrict__ W,       // [64,64]
    const float* __restrict__ evec,    // [32]
    const float* __restrict__ inc,     // [1024,1536]
    const float* __restrict__ lap)     // [1024,1024]
{
    __shared__ __align__(16) float sXT[64][33];   // X transposed, padded
    __shared__ __align__(16) float sW[64 * 64];
    const int bx  = blockIdx.x;
    const int tid = threadIdx.x;

    if (bx < 256) {
        // ----- GEMM role: rows [rb, rb+32) -----
        const int rb = bx * 32;
        #pragma unroll
        for (int t = 0; t < 4; t++)
            ((float4*)sW)[tid + t * 256] = ((const float4*)W)[tid + t * 256];
        #pragma unroll
        for (int t = 0; t < 2; t++) {
            int t2 = tid + t * 256;                  // < 512
            float4 v = ((const float4*)nodes)[rb * 16 + t2];
            int r = t2 >> 4, k = (t2 & 15) << 2;
            sXT[k + 0][r] = v.x; sXT[k + 1][r] = v.y;
            sXT[k + 2][r] = v.z; sXT[k + 3][r] = v.w;
        }
        __syncthreads();

        const int cgrp = tid & 7;     // 8 cols: 8*cgrp ..
        const int r    = tid >> 3;    // row 0..31
        unsigned long long a0 = 0, a1 = 0, a2 = 0, a3 = 0;

        #pragma unroll 8
        for (int k = 0; k < 64; k++) {
            float xs = sXT[k][r];                    // broadcast among 8 lanes
            unsigned long long x2;
            PACK_F32X2(x2, xs, xs);
            const ulonglong2* wp =
                (const ulonglong2*)&sW[k * 64 + cgrp * 8];
            ulonglong2 wa = wp[0];                   // cols 8cgrp .. +3
            ulonglong2 wb = wp[1];                   // cols 8cgrp+4 .. +7
            FMA_F32X2(a0, x2, wa.x, a0);
            FMA_F32X2(a1, x2, wa.y, a1);
            FMA_F32X2(a2, x2, wb.x, a2);
            FMA_F32X2(a3, x2, wb.y, a3);
        }
        float o0,o1,o2,o3,o4,o5,o6,o7;
        UNPACK_F32X2(o0, o1, a0); UNPACK_F32X2(o2, o3, a1);
        UNPACK_F32X2(o4, o5, a2); UNPACK_F32X2(o6, o7, a3);
        float4* gh4 = (float4*)g_h;
        gh4[(rb + r) * 16 + cgrp * 2 + 0] = make_float4(o0, o1, o2, o3);
        gh4[(rb + r) * 16 + cgrp * 2 + 1] = make_float4(o4, o5, o6, o7);
        return;
    }

    if (bx < 352) {
        // ----- extract role: 96 blocks, 16 float4 per thread (2 batches of 8)
        const int t = (bx - 256) * 256 + tid;        // < 24576; 16*24576=393216
        const float4* inc4 = (const float4*)inc;
        #pragma unroll
        for (int half = 0; half < 2; half++) {
            float4 v[8];
            #pragma unroll
            for (int j = 0; j < 8; j++)
                v[j] = inc4[t + (half * 8 + j) * 24576];
            #pragma unroll
            for (int j = 0; j < 8; j++) {
                int idx4 = t + (half * 8 + j) * 24576;
                float vals[4] = {v[j].x, v[j].y, v[j].z, v[j].w};
                #pragma unroll
                for (int c = 0; c < 4; c++) {
                    if (vals[c] != 0.f) {
                        int idx = (idx4 << 2) + c;
                        int i = idx / EE;
                        int e = idx - i * EE;
                        int old = atomicExch(&g_slot[e], i + 1);
                        if (old != 0) {
                            // second endpoint: resolve edge fully
                            int o = old - 1;
                            float lv = lap[i * NN + o];   // == lap[o*NN+i]
                            int di = atomicAdd(&g_deg[i], 1);
                            if (di < MAXDEG) {
                                g_adj[i * MAXDEG + di]  = e | (o << 11);
                                g_adjw[i * MAXDEG + di] = lv;
                            }
                            int dj = atomicAdd(&g_deg[o], 1);
                            if (dj < MAXDEG) {
                                g_adj[o * MAXDEG + dj]  = e | (i << 11);
                                g_adjw[o * MAXDEG + dj] = lv;
                            }
                        }
                    }
                }
            }
        }
        return;
    }

    // ----- ew role: 32 blocks; 4 edges per warp-iter, 8 lanes per edge -----
    {
        const int wg   = (bx - 352) * 8 + (tid >> 5);   // 0..255
        const int lane = tid & 31;
        const int sub  = lane >> 3;
        const int off  = lane & 7;
        float4 ev = ((const float4*)evec)[off];
        #pragma unroll
        for (int it = 0; it < 12; it++) {
            int e = wg * 4 + it * 1024 + sub;            // < 12288
            float4 d = ((const float4*)edges)[e * 8 + off];
            float s = d.x * ev.x + d.y * ev.y + d.z * ev.z + d.w * ev.w;
            s += __shfl_xor_sync(0xffffffffu, s, 4);
            s += __shfl_xor_sync(0xffffffffu, s, 2);
            s += __shfl_xor_sync(0xffffffffu, s, 1);
            if (off == 0) g_ew[e] = s;
        }
    }
}

// ---------------------------------------------------------------------------
// K3: sparse gather, 2 nodes per block, 512 blocks x 512 threads.
// Metadata fill is ONE parallel L2 trip (deg/adj/adjw speculative + lap_ii).
// Persistent-state resets happen ONLY after the fill barrier (no read race).
// ---------------------------------------------------------------------------
__global__ void __launch_bounds__(512) k3(
    const float* __restrict__ lap, float* __restrict__ out)
{
    __shared__ int   sse[2][MAXDEG];
    __shared__ int   sso[2][MAXDEG];
    __shared__ float ssl[2][MAXDEG];
    __shared__ int   sdeg[2];
    __shared__ float slii[2];

    const int i0  = blockIdx.x * 2;
    const int tid = threadIdx.x;

    if (tid < 128) {
        const int g    = tid >> 6;
        const int slot = tid & 63;
        const int i    = i0 + g;
        int   d  = g_deg[i];                      // all three loads independent
        int   pk = g_adj[i * MAXDEG + slot];      // speculative (always valid bits)
        float wv = g_adjw[i * MAXDEG + slot];
        if (d > MAXDEG) d = MAXDEG;
        if (slot == 0) { sdeg[g] = d; slii[g] = lap[i * NN + i]; }
        if (slot < d) {
            sse[g][slot] = pk & 2047;
            sso[g][slot] = pk >> 11;
            ssl[g][slot] = wv;
        }
    }
    __syncthreads();

    // resets strictly AFTER all reads of g_deg (v7's race fixed here)
    if (tid == 0) { g_deg[i0] = 0; g_deg[i0 + 1] = 0; }
    if (tid >= 1 && tid < 4) g_slot[blockIdx.x * 3 + (tid - 1)] = 0; // 512*3=1536

    const int b = tid >> 6;
    const int f = tid & 63;
    const float* hb  = g_h  + b * 65536;
    const float* ewb = g_ew + b * EE;

    const int d0 = sdeg[0], d1 = sdeg[1];
    float hv0 = hb[(i0 + 0) * 64 + f];
    float hv1 = hb[(i0 + 1) * 64 + f];

    float S0 = 0.f, acc0 = 0.f;
    for (int j = 0; j < d0; j++) {
        float w = ewb[sse[0][j]];
        S0   += w;
        acc0 += ssl[0][j] * w * hb[sso[0][j] * 64 + f];
    }
    float S1 = 0.f, acc1 = 0.f;
    for (int j = 0; j < d1; j++) {
        float w = ewb[sse[1][j]];
        S1   += w;
        acc1 += ssl[1][j] * w * hb[sso[1][j] * 64 + f];
    }

    out[(b * NN + i0 + 0) * 64 + f] = slii[0] * S0 * hv0 + acc0;
    out[(b * NN + i0 + 1) * 64 + f] = slii[1] * S1 * hv1 + acc1;
}

// ---------------------------------------------------------------------------
extern "C" void kernel_launch(void* const* d_in, const int* in_sizes, int n_in,
                              void* d_out, int out_size)
{
    const float* nodes = (const float*)d_in[0];
    const float* edges = (const float*)d_in[1];
    const float* W     = (const float*)d_in[2];
    const float* evec  = (const float*)d_in[3];
    const float* inc   = (const float*)d_in[4];
    const float* lap   = (const float*)d_in[5];
    float* out = (float*)d_out;

    (void)in_sizes; (void)n_in; (void)out_size;

    k1<<<384, 256>>>(nodes, edges, W, evec, inc, lap);
    k3<<<512, 512>>>(lap, out);
}

// round 10
// speedup vs baseline: 1.4105x; 1.4105x over previous
// v9 — k1: R5's proven smem layout + FFMA2 arithmetic + 192-block exch-extract;
// k3: v8's 1-trip fill (unchanged, 7.9us).
#include <cuda_runtime.h>

#define NN 1024
#define EE 1536
#define MAXDEG 64

#define FMA_F32X2(d, a, b, c) \
    asm("fma.rn.f32x2 %0, %1, %2, %3;" : "=l"(d) : "l"(a), "l"(b), "l"(c))
#define PACK_F32X2(out, lo, hi) \
    asm("mov.b64 %0, {%1, %2};" : "=l"(out) : "f"(lo), "f"(hi))
#define UNPACK_F32X2(lo, hi, in) \
    asm("mov.b64 {%0, %1}, %2;" : "=f"(lo), "=f"(hi) : "l"(in))

__device__ float g_h[8192 * 64];
__device__ float g_ew[8 * EE];
__device__ int   g_slot[EE];            // exch slot (0 = empty); re-zeroed by k3
__device__ int   g_deg[NN];             // zero at load; re-zeroed by k3
__device__ int   g_adj[NN * MAXDEG];    // packed: e | (o << 11)
__device__ float g_adjw[NN * MAXDEG];   // lap[i, o]

// ---------------------------------------------------------------------------
// K1: 496 blocks x 256 threads.
//   [0,256):   GEMM h = X@W, 32-row tiles, FFMA2 on R5's 4-wavefront layout
//   [256,448): extract (atomicExch edge resolve, lap prefetch), 8 f4/thread
//   [448,496): ew[b,e] = edges[b,e,:] . evec
// ---------------------------------------------------------------------------
__global__ void __launch_bounds__(256) k1(
    const float* __restrict__ nodes,   // [8192,64]
    const float* __restrict__ edges,   // [8,1536,32]
    const float* __restrict__ W,       // [64,64]
    const float* __restrict__ evec,    // [32]
    const float* __restrict__ inc,     // [1024,1536]
    const float* __restrict__ lap)     // [1024,1024]
{
    __shared__ __align__(16) float sX[32][65];    // row-major, padded
    __shared__ __align__(16) float sW[64 * 64];
    const int bx  = blockIdx.x;
    const int tid = threadIdx.x;

    if (bx < 256) {
        // ----- GEMM role: rows [rb, rb+32) -----
        const int rb = bx * 32;
        #pragma unroll
        for (int t = 0; t < 4; t++)
            ((float4*)sW)[tid + t * 256] = ((const float4*)W)[tid + t * 256];
        #pragma unroll
        for (int t = 0; t < 2; t++) {
            int t2 = tid + t * 256;                  // < 512
            float4 v = ((const float4*)nodes)[rb * 16 + t2];
            int r = t2 >> 4, c = (t2 & 15) << 2;
            sX[r][c + 0] = v.x; sX[r][c + 1] = v.y;
            sX[r][c + 2] = v.z; sX[r][c + 3] = v.w;
        }
        __syncthreads();

        const int cg = tid & 15;      // cols 4cg .. 4cg+3
        const int rg = tid >> 4;      // rows 2rg, 2rg+1
        unsigned long long a00 = 0, a01 = 0, a10 = 0, a11 = 0;

        #pragma unroll 8
        for (int k = 0; k < 64; k++) {
            // one float4 LDS (2 wavefronts) + two scalar broadcasts (2 wf)
            ulonglong2 wv = *(const ulonglong2*)&sW[k * 64 + cg * 4];
            float x0 = sX[rg * 2 + 0][k];
            float x1 = sX[rg * 2 + 1][k];
            unsigned long long x0p, x1p;
            PACK_F32X2(x0p, x0, x0);
            PACK_F32X2(x1p, x1, x1);
            FMA_F32X2(a00, x0p, wv.x, a00);
            FMA_F32X2(a01, x0p, wv.y, a01);
            FMA_F32X2(a10, x1p, wv.x, a10);
            FMA_F32X2(a11, x1p, wv.y, a11);
        }
        float c0,c1,c2,c3,d0,d1,d2,d3;
        UNPACK_F32X2(c0, c1, a00); UNPACK_F32X2(c2, c3, a01);
        UNPACK_F32X2(d0, d1, a10); UNPACK_F32X2(d2, d3, a11);
        float4* gh4 = (float4*)g_h;
        gh4[(rb + rg * 2 + 0) * 16 + cg] = make_float4(c0, c1, c2, c3);
        gh4[(rb + rg * 2 + 1) * 16 + cg] = make_float4(d0, d1, d2, d3);
        return;
    }

    if (bx < 448) {
        // ----- extract role: 192 blocks, 8 float4 per thread, batched -----
        const int t = (bx - 256) * 256 + tid;        // < 49152; 8*49152=393216
        const float4* inc4 = (const float4*)inc;
        float4 v[8];
        #pragma unroll
        for (int j = 0; j < 8; j++)
            v[j] = inc4[t + j * 49152];
        #pragma unroll
        for (int j = 0; j < 8; j++) {
            int idx4 = t + j * 49152;
            float vals[4] = {v[j].x, v[j].y, v[j].z, v[j].w};
            #pragma unroll
            for (int c = 0; c < 4; c++) {
                if (vals[c] != 0.f) {
                    int idx = (idx4 << 2) + c;
                    int i = idx / EE;
                    int e = idx - i * EE;
                    int old = atomicExch(&g_slot[e], i + 1);
                    if (old != 0) {
                        int o = old - 1;
                        float lv = lap[i * NN + o];      // == lap[o*NN+i]
                        int di = atomicAdd(&g_deg[i], 1);
                        if (di < MAXDEG) {
                            g_adj[i * MAXDEG + di]  = e | (o << 11);
                            g_adjw[i * MAXDEG + di] = lv;
                        }
                        int dj = atomicAdd(&g_deg[o], 1);
                        if (dj < MAXDEG) {
                            g_adj[o * MAXDEG + dj]  = e | (i << 11);
                            g_adjw[o * MAXDEG + dj] = lv;
                        }
                    }
                }
            }
        }
        return;
    }

    // ----- ew role: 48 blocks; 4 edges per warp-iter, 8 lanes per edge -----
    {
        const int wb   = (bx - 448) * 8 + (tid >> 5);   // 0..383
        const int lane = tid & 31;
        const int sub  = lane >> 3;
        const int off  = lane & 7;
        float4 ev = ((const float4*)evec)[off];
        #pragma unroll
        for (int it = 0; it < 8; it++) {
            int e = wb * 32 + it * 4 + sub;              // < 12288
            float4 d = ((const float4*)edges)[e * 8 + off];
            float s = d.x * ev.x + d.y * ev.y + d.z * ev.z + d.w * ev.w;
            s += __shfl_xor_sync(0xffffffffu, s, 4);
            s += __shfl_xor_sync(0xffffffffu, s, 2);
            s += __shfl_xor_sync(0xffffffffu, s, 1);
            if (off == 0) g_ew[e] = s;
        }
    }
}

// ---------------------------------------------------------------------------
// K3: sparse gather, 2 nodes per block, 512 blocks x 512 threads (v8, proven).
// ---------------------------------------------------------------------------
__global__ void __launch_bounds__(512) k3(
    const float* __restrict__ lap, float* __restrict__ out)
{
    __shared__ int   sse[2][MAXDEG];
    __shared__ int   sso[2][MAXDEG];
    __shared__ float ssl[2][MAXDEG];
    __shared__ int   sdeg[2];
    __shared__ float slii[2];

    const int i0  = blockIdx.x * 2;
    const int tid = threadIdx.x;

    if (tid < 128) {
        const int g    = tid >> 6;
        const int slot = tid & 63;
        const int i    = i0 + g;
        int   d  = g_deg[i];                      // independent loads
        int   pk = g_adj[i * MAXDEG + slot];      // speculative (always valid bits)
        float wv = g_adjw[i * MAXDEG + slot];
        if (d > MAXDEG) d = MAXDEG;
        if (slot == 0) { sdeg[g] = d; slii[g] = lap[i * NN + i]; }
        if (slot < d) {
            sse[g][slot] = pk & 2047;
            sso[g][slot] = pk >> 11;
            ssl[g][slot] = wv;
        }
    }
    __syncthreads();

    // resets strictly AFTER all reads of g_deg
    if (tid == 0) { g_deg[i0] = 0; g_deg[i0 + 1] = 0; }
    if (tid >= 1 && tid < 4) g_slot[blockIdx.x * 3 + (tid - 1)] = 0; // 512*3=1536

    const int b = tid >> 6;
    const int f = tid & 63;
    const float* hb  = g_h  + b * 65536;
    const float* ewb = g_ew + b * EE;

    const int d0 = sdeg[0], d1 = sdeg[1];
    float hv0 = hb[(i0 + 0) * 64 + f];
    float hv1 = hb[(i0 + 1) * 64 + f];

    float S0 = 0.f, acc0 = 0.f;
    for (int j = 0; j < d0; j++) {
        float w = ewb[sse[0][j]];
        S0   += w;
        acc0 += ssl[0][j] * w * hb[sso[0][j] * 64 + f];
    }
    float S1 = 0.f, acc1 = 0.f;
    for (int j = 0; j < d1; j++) {
        float w = ewb[sse[1][j]];
        S1   += w;
        acc1 += ssl[1][j] * w * hb[sso[1][j] * 64 + f];
    }

    out[(b * NN + i0 + 0) * 64 + f] = slii[0] * S0 * hv0 + acc0;
    out[(b * NN + i0 + 1) * 64 + f] = slii[1] * S1 * hv1 + acc1;
}

// ---------------------------------------------------------------------------
extern "C" void kernel_launch(void* const* d_in, const int* in_sizes, int n_in,
                              void* d_out, int out_size)
{
    const float* nodes = (const float*)d_in[0];
    const float* edges = (const float*)d_in[1];
    const float* W     = (const float*)d_in[2];
    const float* evec  = (const float*)d_in[3];
    const float* inc   = (const float*)d_in[4];
    const float* lap   = (const float*)d_in[5];
    float* out = (float*)d_out;

    (void)in_sizes; (void)n_in; (void)out_size;

    k1<<<496, 256>>>(nodes, edges, W, evec, inc, lap);
    k3<<<512, 512>>>(lap, out);
}